// round 11
// baseline (speedup 1.0000x reference)
#include <cuda_runtime.h>

#define NN 40000
#define EE 600000
#define HH 128
#define GG 32
#define CC 6
#define NB2 157   // ceil(NN/256)

// ---- scratch (device globals: no allocation allowed) ----
__device__ float g_b1[NN * HH];
__device__ float g_b2[NN * HH];
__device__ float g_b3[NN * HH];
__device__ float g_dinv[NN];
__device__ float g_emb[GG * HH];
__device__ float g_cnt[GG];
__device__ int   g_deg[NN];
__device__ int   g_rowstart[NN + 1];
__device__ int   g_cursor[NN];
__device__ int   g_csrsrc[EE];
__device__ int   g_bsum[NB2];
__device__ int   g_bscan[NB2];

// ---------------- small utility kernels ----------------
__global__ void k_zero4(float* __restrict__ p, int n4) {
    int i = blockIdx.x * blockDim.x + threadIdx.x;
    if (i < n4) ((float4*)p)[i] = make_float4(0.f, 0.f, 0.f, 0.f);
}

__global__ void k_zero_int(int* __restrict__ p, int n) {
    int i = blockIdx.x * blockDim.x + threadIdx.x;
    if (i < n) p[i] = 0;
}

__global__ void k_hist(const int* __restrict__ dst, int* __restrict__ cnt) {
    int e = blockIdx.x * blockDim.x + threadIdx.x;
    if (e < EE) atomicAdd(&cnt[dst[e]], 1);
}

// ---- 3-stage parallel exclusive scan over degrees ----
__global__ void k_bsum(const int* __restrict__ deg, int* __restrict__ bsum) {
    __shared__ int s[8];
    int i = blockIdx.x * 256 + threadIdx.x;
    int v = (i < NN) ? deg[i] : 0;
#pragma unroll
    for (int o = 16; o > 0; o >>= 1) v += __shfl_down_sync(0xffffffffu, v, o);
    if ((threadIdx.x & 31) == 0) s[threadIdx.x >> 5] = v;
    __syncthreads();
    if (threadIdx.x < 8) {
        int w = s[threadIdx.x];
#pragma unroll
        for (int o = 4; o > 0; o >>= 1) w += __shfl_down_sync(0xffu, w, o);
        if (threadIdx.x == 0) bsum[blockIdx.x] = w;
    }
}

__global__ void k_bscan(const int* __restrict__ bsum, int* __restrict__ bscan) {
    __shared__ int s[256];
    int t = threadIdx.x;
    int v = (t < NB2) ? bsum[t] : 0;
    s[t] = v;
    __syncthreads();
#pragma unroll
    for (int off = 1; off < 256; off <<= 1) {
        int u = 0;
        if (t >= off) u = s[t - off];
        __syncthreads();
        if (t >= off) s[t] += u;
        __syncthreads();
    }
    if (t < NB2) bscan[t] = s[t] - v;    // exclusive
}

__global__ void k_writeoff(const int* __restrict__ deg, const int* __restrict__ bscan,
                           int* __restrict__ row_start, int* __restrict__ cursor,
                           float* __restrict__ dinv) {
    __shared__ int s[256];
    int t = threadIdx.x;
    int i = blockIdx.x * 256 + t;
    int d = (i < NN) ? deg[i] : 0;
    s[t] = d;
    __syncthreads();
#pragma unroll
    for (int off = 1; off < 256; off <<= 1) {
        int u = 0;
        if (t >= off) u = s[t - off];
        __syncthreads();
        if (t >= off) s[t] += u;
        __syncthreads();
    }
    if (i < NN) {
        int excl = s[t] - d + bscan[blockIdx.x];
        row_start[i] = excl;
        cursor[i] = excl;
        dinv[i] = rsqrtf((float)(d + 1));
        if (i == NN - 1) row_start[NN] = EE;
    }
}

__global__ void k_fill(const int* __restrict__ src, const int* __restrict__ dst,
                       int* __restrict__ cursor, int* __restrict__ csr_src) {
    int e = blockIdx.x * blockDim.x + threadIdx.x;
    if (e >= EE) return;
    int s = src[e];
    int d = dst[e];
    int pos = atomicAdd(&cursor[d], 1);
    csr_src[pos] = s;
}

// ---------------- gather: plain neighbor sum (GraphConv), overwrite ----------------
__global__ __launch_bounds__(256) void k_gather_sum(
    const float* __restrict__ x, float* __restrict__ out,
    const int* __restrict__ row_start, const int* __restrict__ csr_src)
{
    int node = (blockIdx.x * blockDim.x + threadIdx.x) >> 5;
    int lane = threadIdx.x & 31;
    if (node >= NN) return;
    int beg = row_start[node];
    int end = row_start[node + 1];

    float4 acc = make_float4(0.f, 0.f, 0.f, 0.f);
    int e = beg;
    for (; e + 1 < end; e += 2) {
        int s0 = csr_src[e], s1 = csr_src[e + 1];
        float4 v0 = ((const float4*)(x + (size_t)s0 * HH))[lane];
        float4 v1 = ((const float4*)(x + (size_t)s1 * HH))[lane];
        acc.x += v0.x + v1.x; acc.y += v0.y + v1.y;
        acc.z += v0.z + v1.z; acc.w += v0.w + v1.w;
    }
    if (e < end) {
        int s0 = csr_src[e];
        float4 v0 = ((const float4*)(x + (size_t)s0 * HH))[lane];
        acc.x += v0.x; acc.y += v0.y; acc.z += v0.z; acc.w += v0.w;
    }
    ((float4*)(out + (size_t)node * HH))[lane] = acc;
}

// ---------------- gather: GCN form  out_i = dinv_i*(y_i + sum y_s) ----------------
__global__ __launch_bounds__(256) void k_gather_gcn(
    const float* __restrict__ y, float* __restrict__ out,
    const int* __restrict__ row_start, const int* __restrict__ csr_src,
    const float* __restrict__ dinv,
    const int* __restrict__ batch, float* __restrict__ emb, float* __restrict__ cnt)
{
    int node = (blockIdx.x * blockDim.x + threadIdx.x) >> 5;
    int lane = threadIdx.x & 31;
    if (node >= NN) return;
    int beg = row_start[node];
    int end = row_start[node + 1];

    float4 acc = ((const float4*)(y + (size_t)node * HH))[lane];   // self term
    int e = beg;
    for (; e + 1 < end; e += 2) {
        int s0 = csr_src[e], s1 = csr_src[e + 1];
        float4 v0 = ((const float4*)(y + (size_t)s0 * HH))[lane];
        float4 v1 = ((const float4*)(y + (size_t)s1 * HH))[lane];
        acc.x += v0.x + v1.x; acc.y += v0.y + v1.y;
        acc.z += v0.z + v1.z; acc.w += v0.w + v1.w;
    }
    if (e < end) {
        int s0 = csr_src[e];
        float4 v0 = ((const float4*)(y + (size_t)s0 * HH))[lane];
        acc.x += v0.x; acc.y += v0.y; acc.z += v0.z; acc.w += v0.w;
    }
    float sc = dinv[node];
    acc.x *= sc; acc.y *= sc; acc.z *= sc; acc.w *= sc;

    if (emb) {
        int g = batch[node];
        atomicAdd(((float4*)(emb + (size_t)g * HH)) + lane, acc);
        if (lane == 0) atomicAdd(&cnt[g], 1.0f);
    } else {
        ((float4*)(out + (size_t)node * HH))[lane] = acc;
    }
}

// ---------------- 3-product BF16 (hi/lo split) tensor-core GEMM, M=64 tiles ----------------
__device__ __forceinline__ unsigned pack_bf16(float lo, float hi) {
    unsigned r;
    asm("cvt.rn.bf16x2.f32 %0, %1, %2;" : "=r"(r) : "f"(hi), "f"(lo));
    return r;
}

__device__ __forceinline__ void mma_bf16(float (&c)[4], const unsigned (&a)[4],
                                         unsigned b0, unsigned b1) {
    asm volatile(
        "mma.sync.aligned.m16n8k16.row.col.f32.bf16.bf16.f32 "
        "{%0,%1,%2,%3},{%4,%5,%6,%7},{%8,%9},{%0,%1,%2,%3};"
        : "+f"(c[0]), "+f"(c[1]), "+f"(c[2]), "+f"(c[3])
        : "r"(a[0]), "r"(a[1]), "r"(a[2]), "r"(a[3]), "r"(b0), "r"(b1));
}

#define AP2 20    // A smem pitch in words
#define WP2 136   // W smem pitch in words
#define ASZ3 (64 * AP2)    // 1280 words
#define WSZ2 (16 * WP2)    // 2176 words

__global__ __launch_bounds__(256, 3) void k_gemm_tc(
    const float* __restrict__ A1, const float* __restrict__ W1,
    const float* __restrict__ A2, const float* __restrict__ W2,
    const float* __restrict__ bias_in,   // applied (with relu) to A1 convert
    const float* __restrict__ bias_out,
    const float* __restrict__ dinv,      // if set: out1 = acc*dinv[row]
    float* __restrict__ out1, int relu_out)
{
    extern __shared__ unsigned sm[];
    unsigned* AH = sm;             // [64][AP2] bf16x2 words (k-pairs)
    unsigned* AL = AH + ASZ3;
    unsigned* WH = AL + ASZ3;      // [16 kpairs][WP2]
    unsigned* WL = WH + WSZ2;

    const int tid = threadIdx.x;
    const int wid = tid >> 5;
    const int lane = tid & 31;
    const int g = lane >> 2;
    const int t = lane & 3;
    const int warpM = wid >> 2;     // 0..1 (x32 rows)
    const int warpN = wid & 3;      // 0..3 (x32 cols)
    const int row0 = blockIdx.x * 64;   // 625 * 64 = 40000 exact

    // A staging coords: rows ar, ar+32
    const int ar = tid >> 3;             // 0..31
    const int ac4 = (tid & 7) * 4;
    const int awb = (tid & 7) * 2;
    // W staging coords: kpairs {wkp, wkp+8}, n cols wn4..wn4+3
    const int wkp = tid >> 5;            // 0..7
    const int wn4 = (tid & 31) * 4;

    float acc[2][4][4];
#pragma unroll
    for (int mi = 0; mi < 2; ++mi)
#pragma unroll
        for (int ni = 0; ni < 4; ++ni)
#pragma unroll
            for (int j = 0; j < 4; ++j) acc[mi][ni][j] = 0.f;

    const int npass = A2 ? 2 : 1;
    const int ntiles = npass * 4;

    float4 rA[2], rW[4];
    {
#pragma unroll
        for (int i = 0; i < 2; ++i)
            rA[i] = *(const float4*)(A1 + (size_t)(row0 + ar + i * 32) * HH + ac4);
        rW[0] = *(const float4*)(W1 + (size_t)(2 * wkp) * HH + wn4);
        rW[1] = *(const float4*)(W1 + (size_t)(2 * wkp + 1) * HH + wn4);
        rW[2] = *(const float4*)(W1 + (size_t)(2 * (wkp + 8)) * HH + wn4);
        rW[3] = *(const float4*)(W1 + (size_t)(2 * (wkp + 8) + 1) * HH + wn4);
    }

#pragma unroll 1
    for (int tile = 0; tile < ntiles; ++tile) {
        const int k0 = (tile & 3) * 32;
        const bool pre = (tile < 4) && (bias_in != nullptr);

        __syncthreads();
        // ---- A tile: split + pack + STS.64 ----
#pragma unroll
        for (int i = 0; i < 2; ++i) {
            float4 v = rA[i];
            if (pre) {
                v.x = fmaxf(v.x + bias_in[k0 + ac4 + 0], 0.f);
                v.y = fmaxf(v.y + bias_in[k0 + ac4 + 1], 0.f);
                v.z = fmaxf(v.z + bias_in[k0 + ac4 + 2], 0.f);
                v.w = fmaxf(v.w + bias_in[k0 + ac4 + 3], 0.f);
            }
            unsigned h0 = pack_bf16(v.x, v.y);
            unsigned h1 = pack_bf16(v.z, v.w);
            float hx = __uint_as_float(h0 << 16);
            float hy = __uint_as_float(h0 & 0xffff0000u);
            float hz = __uint_as_float(h1 << 16);
            float hw = __uint_as_float(h1 & 0xffff0000u);
            unsigned l0 = pack_bf16(v.x - hx, v.y - hy);
            unsigned l1 = pack_bf16(v.z - hz, v.w - hw);
            int bo = (ar + i * 32) * AP2 + awb;
            *(uint2*)&AH[bo] = make_uint2(h0, h1);
            *(uint2*)&AL[bo] = make_uint2(l0, l1);
        }
        // ---- W tile: split + pack + STS.128 ----
#pragma unroll
        for (int j = 0; j < 2; ++j) {
            float4 r0 = rW[2 * j];       // k even row
            float4 r1 = rW[2 * j + 1];   // k odd row
            int kp = wkp + j * 8;
            float e0[4] = {r0.x, r0.y, r0.z, r0.w};
            float e1[4] = {r1.x, r1.y, r1.z, r1.w};
            unsigned hw4[4], lw4[4];
#pragma unroll
            for (int n = 0; n < 4; ++n) {
                unsigned h = pack_bf16(e0[n], e1[n]);   // lo = even k, hi = odd k
                hw4[n] = h;
                float f0 = __uint_as_float(h << 16);
                float f1 = __uint_as_float(h & 0xffff0000u);
                lw4[n] = pack_bf16(e0[n] - f0, e1[n] - f1);
            }
            int bo = kp * WP2 + wn4;
            *(uint4*)&WH[bo] = make_uint4(hw4[0], hw4[1], hw4[2], hw4[3]);
            *(uint4*)&WL[bo] = make_uint4(lw4[0], lw4[1], lw4[2], lw4[3]);
        }
        __syncthreads();

        // ---- prefetch next tile ----
        if (tile + 1 < ntiles) {
            const int nt = tile + 1;
            const float* A = (nt >> 2) ? A2 : A1;
            const float* W = (nt >> 2) ? W2 : W1;
            const int nk0 = (nt & 3) * 32;
#pragma unroll
            for (int i = 0; i < 2; ++i)
                rA[i] = *(const float4*)(A + (size_t)(row0 + ar + i * 32) * HH + nk0 + ac4);
            rW[0] = *(const float4*)(W + (size_t)(nk0 + 2 * wkp) * HH + wn4);
            rW[1] = *(const float4*)(W + (size_t)(nk0 + 2 * wkp + 1) * HH + wn4);
            rW[2] = *(const float4*)(W + (size_t)(nk0 + 2 * (wkp + 8)) * HH + wn4);
            rW[3] = *(const float4*)(W + (size_t)(nk0 + 2 * (wkp + 8) + 1) * HH + wn4);
        }

        // ---- mma: 2 k-chunks of 16 ----
#pragma unroll
        for (int ks = 0; ks < 2; ++ks) {
            int c0 = ks * 8;   // kpair offset
            unsigned ah[2][4], al[2][4];
#pragma unroll
            for (int mi = 0; mi < 2; ++mi) {
                int rb = (warpM * 32 + mi * 16 + g) * AP2 + c0 + t;
                ah[mi][0] = AH[rb];
                ah[mi][1] = AH[rb + 8 * AP2];
                ah[mi][2] = AH[rb + 4];
                ah[mi][3] = AH[rb + 8 * AP2 + 4];
                al[mi][0] = AL[rb];
                al[mi][1] = AL[rb + 8 * AP2];
                al[mi][2] = AL[rb + 4];
                al[mi][3] = AL[rb + 8 * AP2 + 4];
            }
#pragma unroll
            for (int ni = 0; ni < 4; ++ni) {
                int col = warpN * 32 + ni * 8 + g;
                int wb0 = (c0 + t) * WP2 + col;
                int wb1 = wb0 + 4 * WP2;
                unsigned bh0 = WH[wb0], bh1 = WH[wb1];
                unsigned bl0 = WL[wb0], bl1 = WL[wb1];
#pragma unroll
                for (int mi = 0; mi < 2; ++mi) {
                    mma_bf16(acc[mi][ni], ah[mi], bh0, bh1);
                    mma_bf16(acc[mi][ni], ah[mi], bl0, bl1);
                    mma_bf16(acc[mi][ni], al[mi], bh0, bh1);
                }
            }
        }
    }

    // ---- epilogue (no bounds: 625*64 == NN) ----
#pragma unroll
    for (int mi = 0; mi < 2; ++mi) {
        int rbase = row0 + warpM * 32 + mi * 16 + g;
#pragma unroll
        for (int ni = 0; ni < 4; ++ni) {
            int col = warpN * 32 + ni * 8 + 2 * t;
            float c0 = acc[mi][ni][0], c1 = acc[mi][ni][1];
            float c2 = acc[mi][ni][2], c3 = acc[mi][ni][3];
            if (dinv) {
                float w0 = dinv[rbase];
                float w1 = dinv[rbase + 8];
                *(float2*)(out1 + (size_t)rbase * HH + col) = make_float2(c0 * w0, c1 * w0);
                *(float2*)(out1 + (size_t)(rbase + 8) * HH + col) = make_float2(c2 * w1, c3 * w1);
            } else {
                float b0 = bias_out[col], b1 = bias_out[col + 1];
                c0 += b0; c1 += b1; c2 += b0; c3 += b1;
                if (relu_out) {
                    c0 = fmaxf(c0, 0.f); c1 = fmaxf(c1, 0.f);
                    c2 = fmaxf(c2, 0.f); c3 = fmaxf(c3, 0.f);
                }
                *(float2*)(out1 + (size_t)rbase * HH + col) = make_float2(c0, c1);
                *(float2*)(out1 + (size_t)(rbase + 8) * HH + col) = make_float2(c2, c3);
            }
        }
    }
}

// ---------------- final head: mean (+b5) + linear ----------------
__global__ void k_final(const float* __restrict__ lin_w, const float* __restrict__ lin_b,
                        const float* __restrict__ b5,
                        const float* __restrict__ emb, const float* __restrict__ cnt,
                        float* __restrict__ out) {
    __shared__ float se[GG * HH];
    int tid = threadIdx.x;
    for (int i = tid; i < GG * HH; i += blockDim.x) {
        int g = i >> 7;
        int c = i & 127;
        float v = emb[i] / fmaxf(cnt[g], 1.0f) + b5[c];
        se[i] = v;
        out[GG * CC + i] = v;
    }
    __syncthreads();
    for (int i = tid; i < GG * CC; i += blockDim.x) {
        int g = i / CC, c = i % CC;
        float s = lin_b[c];
        const float* e = &se[g * HH];
#pragma unroll 4
        for (int k = 0; k < HH; ++k) s = fmaf(e[k], lin_w[k * CC + c], s);
        out[i] = s;
    }
}

// ---------------- launch ----------------
extern "C" void kernel_launch(void* const* d_in, const int* in_sizes, int n_in,
                              void* d_out, int out_size) {
    const float* x      = (const float*)d_in[0];
    const int*   ei     = (const int*)d_in[1];
    const int*   batch  = (const int*)d_in[2];
    const float* w1r    = (const float*)d_in[3];
    const float* w1rel  = (const float*)d_in[4];
    const float* b1     = (const float*)d_in[5];
    const float* w2r    = (const float*)d_in[6];
    const float* w2rel  = (const float*)d_in[7];
    const float* b2     = (const float*)d_in[8];
    const float* w3     = (const float*)d_in[9];
    const float* b3     = (const float*)d_in[10];
    const float* w4     = (const float*)d_in[11];
    const float* b4     = (const float*)d_in[12];
    const float* w5     = (const float*)d_in[13];
    const float* b5     = (const float*)d_in[14];
    const float* lin_w  = (const float*)d_in[15];
    const float* lin_b  = (const float*)d_in[16];
    float* out = (float*)d_out;

    const int* src = ei;
    const int* dst = ei + EE;

    float *B1, *B2, *B3, *DINV, *EMB, *CNT;
    int *DEG, *ROWS, *CUR, *CSRC, *BSUM, *BSCAN;
    cudaGetSymbolAddress((void**)&B1, g_b1);
    cudaGetSymbolAddress((void**)&B2, g_b2);
    cudaGetSymbolAddress((void**)&B3, g_b3);
    cudaGetSymbolAddress((void**)&DINV, g_dinv);
    cudaGetSymbolAddress((void**)&EMB, g_emb);
    cudaGetSymbolAddress((void**)&CNT, g_cnt);
    cudaGetSymbolAddress((void**)&DEG, g_deg);
    cudaGetSymbolAddress((void**)&ROWS, g_rowstart);
    cudaGetSymbolAddress((void**)&CUR, g_cursor);
    cudaGetSymbolAddress((void**)&CSRC, g_csrsrc);
    cudaGetSymbolAddress((void**)&BSUM, g_bsum);
    cudaGetSymbolAddress((void**)&BSCAN, g_bscan);

    const int SMEM = (2 * ASZ3 + 2 * WSZ2) * 4;   // 27648 B
    cudaFuncSetAttribute(k_gemm_tc, cudaFuncAttributeMaxDynamicSharedMemorySize, SMEM);

    const int NB  = (NN + 255) / 256;          // 157
    const int EB  = (EE + 255) / 256;
    const int GWB = (NN * 32 + 255) / 256;
    const int GMB = NN / 64;                   // 625 exact

    // ---- CSR build (by destination), parallel scan ----
    k_zero_int<<<NB, 256>>>(DEG, NN);
    k_hist<<<EB, 256>>>(dst, DEG);
    k_bsum<<<NB2, 256>>>(DEG, BSUM);
    k_bscan<<<1, 256>>>(BSUM, BSCAN);
    k_writeoff<<<NB2, 256>>>(DEG, BSCAN, ROWS, CUR, DINV);
    k_fill<<<EB, 256>>>(src, dst, CUR, CSRC);

    // zero pooling accumulators early (off critical path)
    k_zero4<<<(GG * HH / 4 + 255) / 256, 256>>>(EMB, GG * HH / 4);
    k_zero4<<<1, 32>>>(CNT, GG / 4);

    // ---- L1: GraphConv ----
    k_gather_sum<<<GWB, 256>>>(x, B1, ROWS, CSRC);
    k_gemm_tc<<<GMB, 256, SMEM>>>(x, w1r, B1, w1rel, nullptr, b1, nullptr, B2, 1);

    // ---- L2: GraphConv ----
    k_gather_sum<<<GWB, 256>>>(B2, B1, ROWS, CSRC);
    k_gemm_tc<<<GMB, 256, SMEM>>>(B2, w2r, B1, w2rel, nullptr, b2, nullptr, B3, 1);

    // ---- L3: GCNConv ----  y = (h@w3)*dinv -> B2 ; out = dinv*(y_i + sum y_s) -> B1
    k_gemm_tc<<<GMB, 256, SMEM>>>(B3, w3, nullptr, nullptr, nullptr, nullptr, DINV, B2, 0);
    k_gather_gcn<<<GWB, 256>>>(B2, B1, ROWS, CSRC, DINV, nullptr, nullptr, nullptr);

    // ---- L4: GCNConv (input +b3, relu on load) ----
    k_gemm_tc<<<GMB, 256, SMEM>>>(B1, w4, nullptr, nullptr, b3, nullptr, DINV, B2, 0);
    k_gather_gcn<<<GWB, 256>>>(B2, B3, ROWS, CSRC, DINV, nullptr, nullptr, nullptr);

    // ---- L5: GCNConv (input +b4, relu on load) + fused pooling ----
    k_gemm_tc<<<GMB, 256, SMEM>>>(B3, w5, nullptr, nullptr, b4, nullptr, DINV, B2, 0);
    k_gather_gcn<<<GWB, 256>>>(B2, nullptr, ROWS, CSRC, DINV, batch, EMB, CNT);

    // ---- head (b5 folded into final mean) ----
    k_final<<<1, 512>>>(lin_w, lin_b, b5, EMB, CNT, out);
}

// round 12
// speedup vs baseline: 1.0069x; 1.0069x over previous
#include <cuda_runtime.h>
#include <cuda_fp16.h>

#define NN 40000
#define EE 600000
#define HH 128
#define GG 32
#define CC 6
#define NB2 157   // ceil(NN/256)

// ---- scratch (device globals: no allocation allowed) ----
__device__ float  g_b1[NN * HH];
__device__ float  g_b2[NN * HH];
__device__ float  g_b3[NN * HH];
__device__ __half g_h16[NN * HH];     // fp16 copy of current gather operand
__device__ float  g_dinv[NN];
__device__ float  g_emb[GG * HH];
__device__ float  g_cnt[GG];
__device__ int    g_deg[NN];
__device__ int    g_rowstart[NN + 1];
__device__ int    g_cursor[NN];
__device__ int    g_csrsrc[EE];
__device__ int    g_bsum[NB2];
__device__ int    g_bscan[NB2];

// ---------------- small utility kernels ----------------
__global__ void k_zero4(float* __restrict__ p, int n4) {
    int i = blockIdx.x * blockDim.x + threadIdx.x;
    if (i < n4) ((float4*)p)[i] = make_float4(0.f, 0.f, 0.f, 0.f);
}

__global__ void k_zero_int(int* __restrict__ p, int n) {
    int i = blockIdx.x * blockDim.x + threadIdx.x;
    if (i < n) p[i] = 0;
}

__global__ void k_hist(const int* __restrict__ dst, int* __restrict__ cnt) {
    int e = blockIdx.x * blockDim.x + threadIdx.x;
    if (e < EE) atomicAdd(&cnt[dst[e]], 1);
}

// x (fp32) -> fp16 copy
__global__ void k_f2h(const float* __restrict__ x, __half* __restrict__ out, int n4) {
    int i = blockIdx.x * blockDim.x + threadIdx.x;
    if (i >= n4) return;
    float4 v = ((const float4*)x)[i];
    __half2 h0 = __floats2half2_rn(v.x, v.y);
    __half2 h1 = __floats2half2_rn(v.z, v.w);
    ((uint2*)out)[i] = make_uint2(*(unsigned*)&h0, *(unsigned*)&h1);
}

// ---- 3-stage parallel exclusive scan over degrees ----
__global__ void k_bsum(const int* __restrict__ deg, int* __restrict__ bsum) {
    __shared__ int s[8];
    int i = blockIdx.x * 256 + threadIdx.x;
    int v = (i < NN) ? deg[i] : 0;
#pragma unroll
    for (int o = 16; o > 0; o >>= 1) v += __shfl_down_sync(0xffffffffu, v, o);
    if ((threadIdx.x & 31) == 0) s[threadIdx.x >> 5] = v;
    __syncthreads();
    if (threadIdx.x < 8) {
        int w = s[threadIdx.x];
#pragma unroll
        for (int o = 4; o > 0; o >>= 1) w += __shfl_down_sync(0xffu, w, o);
        if (threadIdx.x == 0) bsum[blockIdx.x] = w;
    }
}

__global__ void k_bscan(const int* __restrict__ bsum, int* __restrict__ bscan) {
    __shared__ int s[256];
    int t = threadIdx.x;
    int v = (t < NB2) ? bsum[t] : 0;
    s[t] = v;
    __syncthreads();
#pragma unroll
    for (int off = 1; off < 256; off <<= 1) {
        int u = 0;
        if (t >= off) u = s[t - off];
        __syncthreads();
        if (t >= off) s[t] += u;
        __syncthreads();
    }
    if (t < NB2) bscan[t] = s[t] - v;    // exclusive
}

__global__ void k_writeoff(const int* __restrict__ deg, const int* __restrict__ bscan,
                           int* __restrict__ row_start, int* __restrict__ cursor,
                           float* __restrict__ dinv) {
    __shared__ int s[256];
    int t = threadIdx.x;
    int i = blockIdx.x * 256 + t;
    int d = (i < NN) ? deg[i] : 0;
    s[t] = d;
    __syncthreads();
#pragma unroll
    for (int off = 1; off < 256; off <<= 1) {
        int u = 0;
        if (t >= off) u = s[t - off];
        __syncthreads();
        if (t >= off) s[t] += u;
        __syncthreads();
    }
    if (i < NN) {
        int excl = s[t] - d + bscan[blockIdx.x];
        row_start[i] = excl;
        cursor[i] = excl;
        dinv[i] = rsqrtf((float)(d + 1));
        if (i == NN - 1) row_start[NN] = EE;
    }
}

__global__ void k_fill(const int* __restrict__ src, const int* __restrict__ dst,
                       int* __restrict__ cursor, int* __restrict__ csr_src) {
    int e = blockIdx.x * blockDim.x + threadIdx.x;
    if (e >= EE) return;
    int s = src[e];
    int d = dst[e];
    int pos = atomicAdd(&cursor[d], 1);
    csr_src[pos] = s;
}

// ---- fp16 row helpers ----
__device__ __forceinline__ float4 ld_h4(const __half* __restrict__ base, int row, int lane) {
    uint2 u = *(((const uint2*)(base + (size_t)row * HH)) + lane);
    float2 f01 = __half22float2(*reinterpret_cast<__half2*>(&u.x));
    float2 f23 = __half22float2(*reinterpret_cast<__half2*>(&u.y));
    return make_float4(f01.x, f01.y, f23.x, f23.y);
}

// ---------------- gather: plain neighbor sum (GraphConv), fp16 reads ----------------
__global__ __launch_bounds__(256) void k_gather_sum16(
    const __half* __restrict__ xh, float* __restrict__ out,
    const int* __restrict__ row_start, const int* __restrict__ csr_src)
{
    int node = (blockIdx.x * blockDim.x + threadIdx.x) >> 5;
    int lane = threadIdx.x & 31;
    if (node >= NN) return;
    int beg = row_start[node];
    int end = row_start[node + 1];

    float4 acc = make_float4(0.f, 0.f, 0.f, 0.f);
    int e = beg;
    for (; e + 1 < end; e += 2) {
        float4 v0 = ld_h4(xh, csr_src[e], lane);
        float4 v1 = ld_h4(xh, csr_src[e + 1], lane);
        acc.x += v0.x + v1.x; acc.y += v0.y + v1.y;
        acc.z += v0.z + v1.z; acc.w += v0.w + v1.w;
    }
    if (e < end) {
        float4 v0 = ld_h4(xh, csr_src[e], lane);
        acc.x += v0.x; acc.y += v0.y; acc.z += v0.z; acc.w += v0.w;
    }
    ((float4*)(out + (size_t)node * HH))[lane] = acc;
}

// ---------------- gather: GCN  out_i = dinv_i*(y_i(fp32) + sum y_s(fp16)) ----------------
__global__ __launch_bounds__(256) void k_gather_gcn16(
    const float* __restrict__ y, const __half* __restrict__ yh,
    float* __restrict__ out,
    const int* __restrict__ row_start, const int* __restrict__ csr_src,
    const float* __restrict__ dinv,
    const int* __restrict__ batch, float* __restrict__ emb, float* __restrict__ cnt)
{
    int node = (blockIdx.x * blockDim.x + threadIdx.x) >> 5;
    int lane = threadIdx.x & 31;
    if (node >= NN) return;
    int beg = row_start[node];
    int end = row_start[node + 1];

    float4 acc = ((const float4*)(y + (size_t)node * HH))[lane];   // self term fp32
    int e = beg;
    for (; e + 1 < end; e += 2) {
        float4 v0 = ld_h4(yh, csr_src[e], lane);
        float4 v1 = ld_h4(yh, csr_src[e + 1], lane);
        acc.x += v0.x + v1.x; acc.y += v0.y + v1.y;
        acc.z += v0.z + v1.z; acc.w += v0.w + v1.w;
    }
    if (e < end) {
        float4 v0 = ld_h4(yh, csr_src[e], lane);
        acc.x += v0.x; acc.y += v0.y; acc.z += v0.z; acc.w += v0.w;
    }
    float sc = dinv[node];
    acc.x *= sc; acc.y *= sc; acc.z *= sc; acc.w *= sc;

    if (emb) {
        int g = batch[node];
        atomicAdd(((float4*)(emb + (size_t)g * HH)) + lane, acc);
        if (lane == 0) atomicAdd(&cnt[g], 1.0f);
    } else {
        ((float4*)(out + (size_t)node * HH))[lane] = acc;
    }
}

// ---------------- 3-product BF16 (hi/lo split) tensor-core GEMM (R10-proven) ----------------
__device__ __forceinline__ unsigned pack_bf16(float lo, float hi) {
    unsigned r;
    asm("cvt.rn.bf16x2.f32 %0, %1, %2;" : "=r"(r) : "f"(hi), "f"(lo));
    return r;
}

__device__ __forceinline__ void mma_bf16(float (&c)[4], const unsigned (&a)[4],
                                         unsigned b0, unsigned b1) {
    asm volatile(
        "mma.sync.aligned.m16n8k16.row.col.f32.bf16.bf16.f32 "
        "{%0,%1,%2,%3},{%4,%5,%6,%7},{%8,%9},{%0,%1,%2,%3};"
        : "+f"(c[0]), "+f"(c[1]), "+f"(c[2]), "+f"(c[3])
        : "r"(a[0]), "r"(a[1]), "r"(a[2]), "r"(a[3]), "r"(b0), "r"(b1));
}

#define AP2 20    // A smem pitch in words
#define WP2 136   // W smem pitch in words
#define ASZ2 (128 * AP2)   // 2560 words
#define WSZ2 (16 * WP2)    // 2176 words

__global__ __launch_bounds__(256, 2) void k_gemm_tc(
    const float* __restrict__ A1, const float* __restrict__ W1,
    const float* __restrict__ A2, const float* __restrict__ W2,
    const float* __restrict__ bias_in,   // applied (with relu) to A1 convert
    const float* __restrict__ bias_out,
    const float* __restrict__ dinv,      // if set: out = acc*dinv[row]
    float* __restrict__ out1, __half* __restrict__ outh, int relu_out)
{
    extern __shared__ unsigned sm[];
    unsigned* AH = sm;             // [128][AP2] bf16x2 words (k-pairs)
    unsigned* AL = AH + ASZ2;
    unsigned* WH = AL + ASZ2;      // [16 kpairs][WP2]
    unsigned* WL = WH + WSZ2;

    const int tid = threadIdx.x;
    const int wid = tid >> 5;
    const int lane = tid & 31;
    const int g = lane >> 2;
    const int t = lane & 3;
    const int warpM = wid >> 1;
    const int warpN = wid & 1;
    const int row0 = blockIdx.x * 128;

    const int ar = tid >> 3;
    const int ac4 = (tid & 7) * 4;
    const int awb = (tid & 7) * 2;
    const int wkp = tid >> 5;            // 0..7
    const int wn4 = (tid & 31) * 4;

    float acc[2][8][4];
#pragma unroll
    for (int mi = 0; mi < 2; ++mi)
#pragma unroll
        for (int ni = 0; ni < 8; ++ni)
#pragma unroll
            for (int j = 0; j < 4; ++j) acc[mi][ni][j] = 0.f;

    const int npass = A2 ? 2 : 1;
    const int ntiles = npass * 4;

    float4 rA[4], rW[4];
    {
#pragma unroll
        for (int i = 0; i < 4; ++i) {
            int grow = row0 + ar + i * 32;
            rA[i] = make_float4(0.f, 0.f, 0.f, 0.f);
            if (grow < NN) rA[i] = *(const float4*)(A1 + (size_t)grow * HH + ac4);
        }
        rW[0] = *(const float4*)(W1 + (size_t)(2 * wkp) * HH + wn4);
        rW[1] = *(const float4*)(W1 + (size_t)(2 * wkp + 1) * HH + wn4);
        rW[2] = *(const float4*)(W1 + (size_t)(2 * (wkp + 8)) * HH + wn4);
        rW[3] = *(const float4*)(W1 + (size_t)(2 * (wkp + 8) + 1) * HH + wn4);
    }

#pragma unroll 1
    for (int tile = 0; tile < ntiles; ++tile) {
        const int k0 = (tile & 3) * 32;
        const bool pre = (tile < 4) && (bias_in != nullptr);

        __syncthreads();
        // ---- A tile: split + pack + STS.64 ----
#pragma unroll
        for (int i = 0; i < 4; ++i) {
            float4 v = rA[i];
            if (pre) {
                v.x = fmaxf(v.x + bias_in[k0 + ac4 + 0], 0.f);
                v.y = fmaxf(v.y + bias_in[k0 + ac4 + 1], 0.f);
                v.z = fmaxf(v.z + bias_in[k0 + ac4 + 2], 0.f);
                v.w = fmaxf(v.w + bias_in[k0 + ac4 + 3], 0.f);
            }
            unsigned h0 = pack_bf16(v.x, v.y);
            unsigned h1 = pack_bf16(v.z, v.w);
            float hx = __uint_as_float(h0 << 16);
            float hy = __uint_as_float(h0 & 0xffff0000u);
            float hz = __uint_as_float(h1 << 16);
            float hw = __uint_as_float(h1 & 0xffff0000u);
            unsigned l0 = pack_bf16(v.x - hx, v.y - hy);
            unsigned l1 = pack_bf16(v.z - hz, v.w - hw);
            int bo = (ar + i * 32) * AP2 + awb;
            *(uint2*)&AH[bo] = make_uint2(h0, h1);
            *(uint2*)&AL[bo] = make_uint2(l0, l1);
        }
        // ---- W tile: split + pack + STS.128 ----
#pragma unroll
        for (int j = 0; j < 2; ++j) {
            float4 r0 = rW[2 * j];
            float4 r1 = rW[2 * j + 1];
            int kp = wkp + j * 8;
            float e0[4] = {r0.x, r0.y, r0.z, r0.w};
            float e1[4] = {r1.x, r1.y, r1.z, r1.w};
            unsigned hw4[4], lw4[4];
#pragma unroll
            for (int n = 0; n < 4; ++n) {
                unsigned h = pack_bf16(e0[n], e1[n]);
                hw4[n] = h;
                float f0 = __uint_as_float(h << 16);
                float f1 = __uint_as_float(h & 0xffff0000u);
                lw4[n] = pack_bf16(e0[n] - f0, e1[n] - f1);
            }
            int bo = kp * WP2 + wn4;
            *(uint4*)&WH[bo] = make_uint4(hw4[0], hw4[1], hw4[2], hw4[3]);
            *(uint4*)&WL[bo] = make_uint4(lw4[0], lw4[1], lw4[2], lw4[3]);
        }
        __syncthreads();

        // ---- prefetch next tile ----
        if (tile + 1 < ntiles) {
            const int nt = tile + 1;
            const float* A = (nt >> 2) ? A2 : A1;
            const float* W = (nt >> 2) ? W2 : W1;
            const int nk0 = (nt & 3) * 32;
#pragma unroll
            for (int i = 0; i < 4; ++i) {
                int grow = row0 + ar + i * 32;
                rA[i] = make_float4(0.f, 0.f, 0.f, 0.f);
                if (grow < NN) rA[i] = *(const float4*)(A + (size_t)grow * HH + nk0 + ac4);
            }
            rW[0] = *(const float4*)(W + (size_t)(nk0 + 2 * wkp) * HH + wn4);
            rW[1] = *(const float4*)(W + (size_t)(nk0 + 2 * wkp + 1) * HH + wn4);
            rW[2] = *(const float4*)(W + (size_t)(nk0 + 2 * (wkp + 8)) * HH + wn4);
            rW[3] = *(const float4*)(W + (size_t)(nk0 + 2 * (wkp + 8) + 1) * HH + wn4);
        }

        // ---- mma: 2 k-chunks of 16 ----
#pragma unroll
        for (int ks = 0; ks < 2; ++ks) {
            int c0 = ks * 8;
            unsigned ah[2][4], al[2][4];
#pragma unroll
            for (int mi = 0; mi < 2; ++mi) {
                int rb = (warpM * 32 + mi * 16 + g) * AP2 + c0 + t;
                ah[mi][0] = AH[rb];
                ah[mi][1] = AH[rb + 8 * AP2];
                ah[mi][2] = AH[rb + 4];
                ah[mi][3] = AH[rb + 8 * AP2 + 4];
                al[mi][0] = AL[rb];
                al[mi][1] = AL[rb + 8 * AP2];
                al[mi][2] = AL[rb + 4];
                al[mi][3] = AL[rb + 8 * AP2 + 4];
            }
#pragma unroll
            for (int ni = 0; ni < 8; ++ni) {
                int col = warpN * 64 + ni * 8 + g;
                int wb0 = (c0 + t) * WP2 + col;
                int wb1 = wb0 + 4 * WP2;
                unsigned bh0 = WH[wb0], bh1 = WH[wb1];
                unsigned bl0 = WL[wb0], bl1 = WL[wb1];
#pragma unroll
                for (int mi = 0; mi < 2; ++mi) {
                    mma_bf16(acc[mi][ni], ah[mi], bh0, bh1);
                    mma_bf16(acc[mi][ni], ah[mi], bl0, bl1);
                    mma_bf16(acc[mi][ni], al[mi], bh0, bh1);
                }
            }
        }
    }

    // ---- epilogue: fp32 out + fp16 copy ----
#pragma unroll
    for (int mi = 0; mi < 2; ++mi) {
        int rbase = row0 + warpM * 32 + mi * 16 + g;
#pragma unroll
        for (int ni = 0; ni < 8; ++ni) {
            int col = warpN * 64 + ni * 8 + 2 * t;
            float c0 = acc[mi][ni][0], c1 = acc[mi][ni][1];
            float c2 = acc[mi][ni][2], c3 = acc[mi][ni][3];
            if (dinv) {
                if (rbase < NN) {
                    float w = dinv[rbase];
                    c0 *= w; c1 *= w;
                    *(float2*)(out1 + (size_t)rbase * HH + col) = make_float2(c0, c1);
                    *(__half2*)(outh + (size_t)rbase * HH + col) = __floats2half2_rn(c0, c1);
                }
                if (rbase + 8 < NN) {
                    float w = dinv[rbase + 8];
                    c2 *= w; c3 *= w;
                    *(float2*)(out1 + (size_t)(rbase + 8) * HH + col) = make_float2(c2, c3);
                    *(__half2*)(outh + (size_t)(rbase + 8) * HH + col) = __floats2half2_rn(c2, c3);
                }
            } else {
                float b0 = bias_out[col], b1 = bias_out[col + 1];
                c0 += b0; c1 += b1; c2 += b0; c3 += b1;
                if (relu_out) {
                    c0 = fmaxf(c0, 0.f); c1 = fmaxf(c1, 0.f);
                    c2 = fmaxf(c2, 0.f); c3 = fmaxf(c3, 0.f);
                }
                if (rbase < NN) {
                    *(float2*)(out1 + (size_t)rbase * HH + col) = make_float2(c0, c1);
                    if (outh)
                        *(__half2*)(outh + (size_t)rbase * HH + col) = __floats2half2_rn(c0, c1);
                }
                if (rbase + 8 < NN) {
                    *(float2*)(out1 + (size_t)(rbase + 8) * HH + col) = make_float2(c2, c3);
                    if (outh)
                        *(__half2*)(outh + (size_t)(rbase + 8) * HH + col) = __floats2half2_rn(c2, c3);
                }
            }
        }
    }
}

// ---------------- final head: mean (+b5) + linear ----------------
__global__ void k_final(const float* __restrict__ lin_w, const float* __restrict__ lin_b,
                        const float* __restrict__ b5,
                        const float* __restrict__ emb, const float* __restrict__ cnt,
                        float* __restrict__ out) {
    __shared__ float se[GG * HH];
    int tid = threadIdx.x;
    for (int i = tid; i < GG * HH; i += blockDim.x) {
        int g = i >> 7;
        int c = i & 127;
        float v = emb[i] / fmaxf(cnt[g], 1.0f) + b5[c];
        se[i] = v;
        out[GG * CC + i] = v;
    }
    __syncthreads();
    for (int i = tid; i < GG * CC; i += blockDim.x) {
        int g = i / CC, c = i % CC;
        float s = lin_b[c];
        const float* e = &se[g * HH];
#pragma unroll 4
        for (int k = 0; k < HH; ++k) s = fmaf(e[k], lin_w[k * CC + c], s);
        out[i] = s;
    }
}

// ---------------- launch ----------------
extern "C" void kernel_launch(void* const* d_in, const int* in_sizes, int n_in,
                              void* d_out, int out_size) {
    const float* x      = (const float*)d_in[0];
    const int*   ei     = (const int*)d_in[1];
    const int*   batch  = (const int*)d_in[2];
    const float* w1r    = (const float*)d_in[3];
    const float* w1rel  = (const float*)d_in[4];
    const float* b1     = (const float*)d_in[5];
    const float* w2r    = (const float*)d_in[6];
    const float* w2rel  = (const float*)d_in[7];
    const float* b2     = (const float*)d_in[8];
    const float* w3     = (const float*)d_in[9];
    const float* b3     = (const float*)d_in[10];
    const float* w4     = (const float*)d_in[11];
    const float* b4     = (const float*)d_in[12];
    const float* w5     = (const float*)d_in[13];
    const float* b5     = (const float*)d_in[14];
    const float* lin_w  = (const float*)d_in[15];
    const float* lin_b  = (const float*)d_in[16];
    float* out = (float*)d_out;

    const int* src = ei;
    const int* dst = ei + EE;

    float *B1, *B2, *B3, *DINV, *EMB, *CNT;
    __half* H16;
    int *DEG, *ROWS, *CUR, *CSRC, *BSUM, *BSCAN;
    cudaGetSymbolAddress((void**)&B1, g_b1);
    cudaGetSymbolAddress((void**)&B2, g_b2);
    cudaGetSymbolAddress((void**)&B3, g_b3);
    cudaGetSymbolAddress((void**)&H16, g_h16);
    cudaGetSymbolAddress((void**)&DINV, g_dinv);
    cudaGetSymbolAddress((void**)&EMB, g_emb);
    cudaGetSymbolAddress((void**)&CNT, g_cnt);
    cudaGetSymbolAddress((void**)&DEG, g_deg);
    cudaGetSymbolAddress((void**)&ROWS, g_rowstart);
    cudaGetSymbolAddress((void**)&CUR, g_cursor);
    cudaGetSymbolAddress((void**)&CSRC, g_csrsrc);
    cudaGetSymbolAddress((void**)&BSUM, g_bsum);
    cudaGetSymbolAddress((void**)&BSCAN, g_bscan);

    const int SMEM = (2 * ASZ2 + 2 * WSZ2) * 4;   // 37888 B
    cudaFuncSetAttribute(k_gemm_tc, cudaFuncAttributeMaxDynamicSharedMemorySize, SMEM);

    const int NB  = (NN + 255) / 256;          // 157
    const int EB  = (EE + 255) / 256;
    const int GWB = (NN * 32 + 255) / 256;
    const int GMB = (NN + 127) / 128;          // 313
    const int NH4 = NN * HH / 4;

    // ---- CSR build (by destination), parallel scan; x -> fp16 ----
    k_zero_int<<<NB, 256>>>(DEG, NN);
    k_hist<<<EB, 256>>>(dst, DEG);
    k_f2h<<<(NH4 + 255) / 256, 256>>>(x, H16, NH4);
    k_bsum<<<NB2, 256>>>(DEG, BSUM);
    k_bscan<<<1, 256>>>(BSUM, BSCAN);
    k_writeoff<<<NB2, 256>>>(DEG, BSCAN, ROWS, CUR, DINV);
    k_fill<<<EB, 256>>>(src, dst, CUR, CSRC);

    // zero pooling accumulators early (off critical path)
    k_zero4<<<(GG * HH / 4 + 255) / 256, 256>>>(EMB, GG * HH / 4);
    k_zero4<<<1, 32>>>(CNT, GG / 4);

    // ---- L1: GraphConv ----
    k_gather_sum16<<<GWB, 256>>>(H16, B1, ROWS, CSRC);
    k_gemm_tc<<<GMB, 256, SMEM>>>(x, w1r, B1, w1rel, nullptr, b1, nullptr, B2, H16, 1);

    // ---- L2: GraphConv ----
    k_gather_sum16<<<GWB, 256>>>(H16, B1, ROWS, CSRC);
    k_gemm_tc<<<GMB, 256, SMEM>>>(B2, w2r, B1, w2rel, nullptr, b2, nullptr, B3, H16, 1);

    // ---- L3: GCNConv ----  y = (h@w3)*dinv -> B2(fp32)+H16 ; out -> B1
    k_gemm_tc<<<GMB, 256, SMEM>>>(B3, w3, nullptr, nullptr, nullptr, nullptr, DINV, B2, H16, 0);
    k_gather_gcn16<<<GWB, 256>>>(B2, H16, B1, ROWS, CSRC, DINV, nullptr, nullptr, nullptr);

    // ---- L4: GCNConv (input +b3, relu on load) ----
    k_gemm_tc<<<GMB, 256, SMEM>>>(B1, w4, nullptr, nullptr, b3, nullptr, DINV, B2, H16, 0);
    k_gather_gcn16<<<GWB, 256>>>(B2, H16, B3, ROWS, CSRC, DINV, nullptr, nullptr, nullptr);

    // ---- L5: GCNConv (input +b4, relu on load) + fused pooling ----
    k_gemm_tc<<<GMB, 256, SMEM>>>(B3, w5, nullptr, nullptr, b4, nullptr, DINV, B2, H16, 0);
    k_gather_gcn16<<<GWB, 256>>>(B2, H16, nullptr, ROWS, CSRC, DINV, batch, EMB, CNT);

    // ---- head (b5 folded into final mean) ----
    k_final<<<1, 512>>>(lin_w, lin_b, b5, EMB, CNT, out);
}